// round 8
// baseline (speedup 1.0000x reference)
#include <cuda_runtime.h>
#include <math.h>

// Problem constants
#define Bb 2
#define Ss 2048
#define Dd 1024
#define Hh 16
#define HDc 64
#define SCALE 0.125f  /* 1/sqrt(64) */

// Scratch (no allocations allowed -> device globals)
__device__ float g_Q[Bb * Hh * Ss * HDc];     // [B,H,S,HD]
__device__ float g_K[Bb * Hh * Ss * HDc];     // [B,H,S,HD]
__device__ float g_attn[Bb * Ss * Dd];        // [B,S,D]

// ---------------------------------------------------------------------------
// tf32 helpers: mma.m16n8k8 + 3xTF32 split for ~fp32 accuracy.
// hi/lo pairs are PRE-SPLIT into smem as uint2{hi,lo}; mainloop = LDS + MMA.
// Fragment layouts (m16n8k8 tf32, row.col): g = lane>>2, tg = lane&3
//   A(16x8): (g,tg) (g+8,tg) (g,tg+4) (g+8,tg+4)
//   B(8x8):  (tg,g) (tg+4,g)
//   C(16x8): (g,2tg) (g,2tg+1) (g+8,2tg) (g+8,2tg+1)
// ---------------------------------------------------------------------------
__device__ __forceinline__ unsigned f2tf(float f) {
    unsigned u; asm("cvt.rna.tf32.f32 %0, %1;" : "=r"(u) : "f"(f)); return u;
}
__device__ __forceinline__ uint2 splitu(float a) {
    uint2 r; r.x = f2tf(a);
    r.y = f2tf(a - __uint_as_float(r.x));
    return r;
}
__device__ __forceinline__ void mma8(float* c, unsigned a0, unsigned a1, unsigned a2,
                                     unsigned a3, unsigned b0, unsigned b1) {
    asm volatile("mma.sync.aligned.m16n8k8.row.col.f32.tf32.tf32.f32 "
                 "{%0,%1,%2,%3}, {%4,%5,%6,%7}, {%8,%9}, {%0,%1,%2,%3};"
                 : "+f"(c[0]), "+f"(c[1]), "+f"(c[2]), "+f"(c[3])
                 : "r"(a0), "r"(a1), "r"(a2), "r"(a3), "r"(b0), "r"(b1));
}
__device__ __forceinline__ void mma_x3(float* c, const uint2 a[4], uint2 b0, uint2 b1) {
    mma8(c, a[0].x, a[1].x, a[2].x, a[3].x, b0.x, b1.x);
    mma8(c, a[0].x, a[1].x, a[2].x, a[3].x, b0.y, b1.y);
    mma8(c, a[0].y, a[1].y, a[2].y, a[3].y, b0.x, b1.x);
}

// ---------------------------------------------------------------------------
// Projection GEMM (3xTF32, pre-split tiles): C = A @ W^T + bias
// BM=128, BN=64, BK=32, 256 threads = 8 warps (4m x 2n), warp tile 32x32.
// smem: As uint2[128][36], Ws uint2[64][36]  (55.3 KB dynamic, 2 CTAs/SM)
// stride 36 uint2 -> all LDS.64 fragment phases conflict-free.
// mode 0: scatter into g_Q / g_K; mode 1: A = g_attn, plain write to Cout.
// ---------------------------------------------------------------------------
#define PROJ_SMEM ((128 * 36 + 64 * 36) * 8)

__global__ void __launch_bounds__(256)
proj_k(const float* __restrict__ A, const float* __restrict__ Wt,
       const float* __restrict__ bias, float* __restrict__ Cout, int mode)
{
    extern __shared__ uint2 psm[];
    uint2* As = psm;              // [128][36]
    uint2* Ws = psm + 128 * 36;   // [64][36]

    const float* __restrict__ Ain = (mode == 1) ? g_attn : A;

    const int tid  = threadIdx.x;
    const int lane = tid & 31, warp = tid >> 5;
    const int g = lane >> 2, tg = lane & 3;
    const int wm = (warp >> 1) * 32;   // 0,32,64,96
    const int wn = (warp & 1) * 32;    // 0,32
    const int rowBase = blockIdx.y * 128;
    const int colBase = blockIdx.x * 64;

    float acc[2][4][4];
#pragma unroll
    for (int mt = 0; mt < 2; mt++)
#pragma unroll
        for (int nt = 0; nt < 4; nt++)
#pragma unroll
            for (int j = 0; j < 4; j++) acc[mt][nt][j] = 0.f;

    for (int kt = 0; kt < Dd; kt += 32) {
        __syncthreads();
        // Load + split A tile: 128x32 floats
#pragma unroll
        for (int t = 0; t < 4; t++) {
            int idx = tid + t * 256;
            int r = idx >> 3, kq = (idx & 7) << 2;
            float4 v = *(const float4*)(Ain + (size_t)(rowBase + r) * Dd + kt + kq);
            As[r * 36 + kq]     = splitu(v.x);
            As[r * 36 + kq + 1] = splitu(v.y);
            As[r * 36 + kq + 2] = splitu(v.z);
            As[r * 36 + kq + 3] = splitu(v.w);
        }
        // Load + split W tile: 64x32 floats
#pragma unroll
        for (int t = 0; t < 2; t++) {
            int idx = tid + t * 256;
            int r = idx >> 3, kq = (idx & 7) << 2;
            float4 v = *(const float4*)(Wt + (size_t)(colBase + r) * Dd + kt + kq);
            Ws[r * 36 + kq]     = splitu(v.x);
            Ws[r * 36 + kq + 1] = splitu(v.y);
            Ws[r * 36 + kq + 2] = splitu(v.z);
            Ws[r * 36 + kq + 3] = splitu(v.w);
        }
        __syncthreads();

#pragma unroll
        for (int ks = 0; ks < 4; ks++) {
            const int k0 = ks * 8;
            uint2 af[2][4];
#pragma unroll
            for (int mt = 0; mt < 2; mt++) {
                int r0 = wm + mt * 16 + g;
                af[mt][0] = As[r0 * 36 + k0 + tg];
                af[mt][1] = As[(r0 + 8) * 36 + k0 + tg];
                af[mt][2] = As[r0 * 36 + k0 + tg + 4];
                af[mt][3] = As[(r0 + 8) * 36 + k0 + tg + 4];
            }
#pragma unroll
            for (int nt = 0; nt < 4; nt++) {
                int c0 = wn + nt * 8 + g;
                uint2 b0 = Ws[c0 * 36 + k0 + tg];
                uint2 b1 = Ws[c0 * 36 + k0 + tg + 4];
                mma_x3(acc[0][nt], af[0], b0, b1);
                mma_x3(acc[1][nt], af[1], b0, b1);
            }
        }
    }

    // Epilogue: bias + scatter
#pragma unroll
    for (int mt = 0; mt < 2; mt++)
#pragma unroll
    for (int nt = 0; nt < 4; nt++)
#pragma unroll
    for (int hf = 0; hf < 2; hf++) {
        int r = rowBase + wm + mt * 16 + g + hf * 8;
        int c = colBase + wn + nt * 8 + 2 * tg;
        float2 bv = *(const float2*)(bias + c);
        float2 v = make_float2(acc[mt][nt][hf * 2] + bv.x,
                               acc[mt][nt][hf * 2 + 1] + bv.y);
        int bb = r >> 11, s = r & 2047;
        if (mode == 0) {
            if (c < Dd) {
                int h = c >> 6, d0 = c & 63;
                *(float2*)&g_Q[(((size_t)(bb * Hh + h)) * Ss + s) * HDc + d0] = v;
            } else {
                int c2 = c - Dd; int h = c2 >> 6, d0 = c2 & 63;
                *(float2*)&g_K[(((size_t)(bb * Hh + h)) * Ss + s) * HDc + d0] = v;
            }
        } else {
            *(float2*)(Cout + (size_t)r * Dd + c) = v;
        }
    }
}

// ---------------------------------------------------------------------------
// Tensor-core flash attention, masked L1 renorm, pre-split hi/lo tiles.
// CTA = (b,h, 128-query tile), 256 threads = 8 warps; warp w owns rows
// [16w,16w+16). Q split ONCE per CTA; K/V split once per tile at load;
// P plain-float (written/read by same warp, split on read).
// smem: Qs uint2[128][68] + Ks,Vs uint2[64][68] + Ps float[128][68] = 170 KB.
// ---------------------------------------------------------------------------
#define ATTN_SMEM ((128 * 68 + 64 * 68 + 64 * 68) * 8 + 128 * 68 * 4)

__global__ void __launch_bounds__(256)
attn_k(const float* __restrict__ Vg, const float* __restrict__ Mg)
{
    extern __shared__ char smraw[];
    uint2* Qs = (uint2*)smraw;        // [128][68] hi/lo
    uint2* Ks = Qs + 128 * 68;        // [64][68]  hi/lo, [key][d]
    uint2* Vs = Ks + 64 * 68;         // [64][68]  hi/lo, [key][d]
    float* Ps = (float*)(Vs + 64 * 68); // [128][68] plain

    const int tid  = threadIdx.x;
    const int lane = tid & 31, w = tid >> 5;
    const int g = lane >> 2, tg = lane & 3;
    const int bh = blockIdx.y, bb = bh >> 4, h = bh & 15;
    const int q0 = blockIdx.x * 128;
    const int r0 = w * 16 + g;        // this thread's base row (and r0+8)

    // Load + split Q tile once: 128x64 floats
    const float* __restrict__ gQ = g_Q + ((size_t)bh * Ss + q0) * HDc;
#pragma unroll
    for (int t = 0; t < 8; t++) {
        int idx = tid + t * 256;
        int r = idx >> 4, d4 = (idx & 15) << 2;
        float4 v = *(const float4*)(gQ + (size_t)r * HDc + d4);
        Qs[r * 68 + d4]     = splitu(v.x);
        Qs[r * 68 + d4 + 1] = splitu(v.y);
        Qs[r * 68 + d4 + 2] = splitu(v.z);
        Qs[r * 68 + d4 + 3] = splitu(v.w);
    }

    float m_cur[2] = {-1e30f, -1e30f}, Zacc[2] = {0.f, 0.f}, Wacc[2] = {0.f, 0.f};
    float oacc[8][4];
#pragma unroll
    for (int nt = 0; nt < 8; nt++)
#pragma unroll
        for (int j = 0; j < 4; j++) oacc[nt][j] = 0.f;

    const float* __restrict__ mrow0 = Mg + ((size_t)(bb * Ss + q0 + r0)) * Ss;
    const float* __restrict__ mrow1 = mrow0 + (size_t)8 * Ss;

    for (int kt = 0; kt < Ss; kt += 64) {
        __syncthreads();   // prev iter's GEMMs done with Ks/Vs (+ Q split visible)

        // Load + split K tile [key][d]: 64x64 floats
        const float* __restrict__ gK = g_K + ((size_t)bh * Ss + kt) * HDc;
#pragma unroll
        for (int t = 0; t < 4; t++) {
            int idx = tid + t * 256;
            int r = idx >> 4, d4 = (idx & 15) << 2;
            float4 v = *(const float4*)(gK + (size_t)r * HDc + d4);
            Ks[r * 68 + d4]     = splitu(v.x);
            Ks[r * 68 + d4 + 1] = splitu(v.y);
            Ks[r * 68 + d4 + 2] = splitu(v.z);
            Ks[r * 68 + d4 + 3] = splitu(v.w);
        }
        // Load + split V tile [key][d]
        const float* __restrict__ gV = Vg + (((size_t)(bb * Ss + kt)) * Hh + h) * HDc;
#pragma unroll
        for (int t = 0; t < 4; t++) {
            int idx = tid + t * 256;
            int r = idx >> 4, d4 = (idx & 15) << 2;
            float4 v = *(const float4*)(gV + (size_t)r * (Hh * HDc) + d4);
            Vs[r * 68 + d4]     = splitu(v.x);
            Vs[r * 68 + d4 + 1] = splitu(v.y);
            Vs[r * 68 + d4 + 2] = splitu(v.z);
            Vs[r * 68 + d4 + 3] = splitu(v.w);
        }
        // Prefetch mask fragments (hidden under GEMM1)
        float2 mk0[8], mk1[8];
#pragma unroll
        for (int nt = 0; nt < 8; nt++) {
            mk0[nt] = *(const float2*)(mrow0 + kt + nt * 8 + 2 * tg);
            mk1[nt] = *(const float2*)(mrow1 + kt + nt * 8 + 2 * tg);
        }
        __syncthreads();

        // GEMM1: S = Q K^T
        float sfr[8][4];
#pragma unroll
        for (int nt = 0; nt < 8; nt++)
#pragma unroll
            for (int j = 0; j < 4; j++) sfr[nt][j] = 0.f;
#pragma unroll
        for (int ks = 0; ks < 8; ks++) {
            const int k0 = ks * 8;
            uint2 qf[4];
            qf[0] = Qs[r0 * 68 + k0 + tg];
            qf[1] = Qs[(r0 + 8) * 68 + k0 + tg];
            qf[2] = Qs[r0 * 68 + k0 + tg + 4];
            qf[3] = Qs[(r0 + 8) * 68 + k0 + tg + 4];
#pragma unroll
            for (int nt = 0; nt < 8; nt++) {
                int c = nt * 8 + g;
                uint2 b0 = Ks[c * 68 + k0 + tg];
                uint2 b1 = Ks[c * 68 + k0 + tg + 4];
                mma_x3(sfr[nt], qf, b0, b1);
            }
        }

        // Softmax stats (rows r0 and r0+8; reduce over 4-thread group)
        float rmax0 = -1e30f, rmax1 = -1e30f;
#pragma unroll
        for (int nt = 0; nt < 8; nt++) {
            sfr[nt][0] *= SCALE; sfr[nt][1] *= SCALE;
            sfr[nt][2] *= SCALE; sfr[nt][3] *= SCALE;
            rmax0 = fmaxf(rmax0, fmaxf(sfr[nt][0], sfr[nt][1]));
            rmax1 = fmaxf(rmax1, fmaxf(sfr[nt][2], sfr[nt][3]));
        }
        rmax0 = fmaxf(rmax0, __shfl_xor_sync(0xffffffffu, rmax0, 1));
        rmax0 = fmaxf(rmax0, __shfl_xor_sync(0xffffffffu, rmax0, 2));
        rmax1 = fmaxf(rmax1, __shfl_xor_sync(0xffffffffu, rmax1, 1));
        rmax1 = fmaxf(rmax1, __shfl_xor_sync(0xffffffffu, rmax1, 2));
        float mn0 = fmaxf(m_cur[0], rmax0), mn1 = fmaxf(m_cur[1], rmax1);
        float al0 = __expf(m_cur[0] - mn0), al1 = __expf(m_cur[1] - mn1);

        float zp0 = 0.f, zp1 = 0.f, wp0 = 0.f, wp1 = 0.f;
#pragma unroll
        for (int nt = 0; nt < 8; nt++) {
            float p00 = __expf(sfr[nt][0] - mn0), p01 = __expf(sfr[nt][1] - mn0);
            float p10 = __expf(sfr[nt][2] - mn1), p11 = __expf(sfr[nt][3] - mn1);
            zp0 += p00 + p01; zp1 += p10 + p11;
            float w00 = p00 * mk0[nt].x, w01 = p01 * mk0[nt].y;
            float w10 = p10 * mk1[nt].x, w11 = p11 * mk1[nt].y;
            wp0 += w00 + w01; wp1 += w10 + w11;
            int c = nt * 8 + 2 * tg;
            *(float2*)&Ps[r0 * 68 + c]       = make_float2(w00, w01);
            *(float2*)&Ps[(r0 + 8) * 68 + c] = make_float2(w10, w11);
        }
        zp0 += __shfl_xor_sync(0xffffffffu, zp0, 1); zp0 += __shfl_xor_sync(0xffffffffu, zp0, 2);
        zp1 += __shfl_xor_sync(0xffffffffu, zp1, 1); zp1 += __shfl_xor_sync(0xffffffffu, zp1, 2);
        wp0 += __shfl_xor_sync(0xffffffffu, wp0, 1); wp0 += __shfl_xor_sync(0xffffffffu, wp0, 2);
        wp1 += __shfl_xor_sync(0xffffffffu, wp1, 1); wp1 += __shfl_xor_sync(0xffffffffu, wp1, 2);
        Zacc[0] = Zacc[0] * al0 + zp0; Zacc[1] = Zacc[1] * al1 + zp1;
        Wacc[0] = Wacc[0] * al0 + wp0; Wacc[1] = Wacc[1] * al1 + wp1;
        m_cur[0] = mn0; m_cur[1] = mn1;
        __syncwarp();   // Ps rows are warp-private; make stores visible in-warp

        // GEMM2: O = O*alpha + P V
#pragma unroll
        for (int nt = 0; nt < 8; nt++) {
            oacc[nt][0] *= al0; oacc[nt][1] *= al0;
            oacc[nt][2] *= al1; oacc[nt][3] *= al1;
        }
#pragma unroll
        for (int ks = 0; ks < 8; ks++) {
            const int k0 = ks * 8;
            uint2 pf[4];
            pf[0] = splitu(Ps[r0 * 68 + k0 + tg]);
            pf[1] = splitu(Ps[(r0 + 8) * 68 + k0 + tg]);
            pf[2] = splitu(Ps[r0 * 68 + k0 + tg + 4]);
            pf[3] = splitu(Ps[(r0 + 8) * 68 + k0 + tg + 4]);
#pragma unroll
            for (int nt = 0; nt < 8; nt++) {
                uint2 b0 = Vs[(k0 + tg) * 68 + nt * 8 + g];
                uint2 b1 = Vs[(k0 + tg + 4) * 68 + nt * 8 + g];
                mma_x3(oacc[nt], pf, b0, b1);
            }
        }
    }

    // Epilogue: divide and write [B,S,D]
    float inv0 = 1.f / (Wacc[0] + 1e-8f * Zacc[0]);
    float inv1 = 1.f / (Wacc[1] + 1e-8f * Zacc[1]);
    int s0 = q0 + r0;
#pragma unroll
    for (int nt = 0; nt < 8; nt++) {
        int c = h * HDc + nt * 8 + 2 * tg;
        *(float2*)&g_attn[((size_t)(bb * Ss + s0)) * Dd + c] =
            make_float2(oacc[nt][0] * inv0, oacc[nt][1] * inv0);
        *(float2*)&g_attn[((size_t)(bb * Ss + s0 + 8)) * Dd + c] =
            make_float2(oacc[nt][2] * inv1, oacc[nt][3] * inv1);
    }
}

// ---------------------------------------------------------------------------
extern "C" void kernel_launch(void* const* d_in, const int* in_sizes, int n_in,
                              void* d_out, int out_size)
{
    const float* x     = (const float*)d_in[0];
    const float* V     = (const float*)d_in[1];
    const float* M     = (const float*)d_in[2];
    const float* in_w  = (const float*)d_in[3];
    const float* in_b  = (const float*)d_in[4];
    const float* out_w = (const float*)d_in[5];
    const float* out_b = (const float*)d_in[6];
    float* out = (float*)d_out;

    // Opt in to large dynamic smem (host attribute set, not a stream op).
    cudaFuncSetAttribute((const void*)proj_k,
                         cudaFuncAttributeMaxDynamicSharedMemorySize, PROJ_SMEM);
    cudaFuncSetAttribute((const void*)attn_k,
                         cudaFuncAttributeMaxDynamicSharedMemorySize, ATTN_SMEM);

    // 1) QK projection: [4096,1024] x [2048,1024]^T -> scatter to g_Q/g_K
    proj_k<<<dim3(32, 32), 256, PROJ_SMEM>>>(x, in_w, in_b, nullptr, 0);
    // 2) masked-renorm flash attention (3xTF32, pre-split tiles) -> g_attn
    attn_k<<<dim3(16, 32), 256, ATTN_SMEM>>>(V, M);
    // 3) out projection: g_attn x out_w^T + out_b -> d_out
    proj_k<<<dim3(16, 32), 256, PROJ_SMEM>>>(nullptr, out_w, out_b, out, 1);
}

// round 9
// speedup vs baseline: 2.0183x; 2.0183x over previous
#include <cuda_runtime.h>
#include <math.h>

// Problem constants
#define Bb 2
#define Ss 2048
#define Dd 1024
#define Hh 16
#define HDc 64
#define SCALE 0.125f  /* 1/sqrt(64) */

// Scratch (no allocations allowed -> device globals)
__device__ float g_Q[Bb * Hh * Ss * HDc];     // [B,H,S,HD]
__device__ float g_K[Bb * Hh * Ss * HDc];     // [B,H,S,HD]
__device__ float g_attn[Bb * Ss * Dd];        // [B,S,D]

// ---------------------------------------------------------------------------
// bf16x3 helpers: mma.m16n8k16.bf16 + 2-way bf16 split (hi+lo ~ 16 mantissa
// bits; dropped lo*lo term ~2^-17 relative). Tiles stored as packed pairs:
// uint2{ hi_pair(bf16x2), lo_pair(bf16x2) } covering 2 consecutive k values.
// Fragment layouts (m16n8k16, row.col): g = lane>>2, tg = lane&3, pair units:
//   A: a0=A[g][pair tg] a1=A[g+8][tg] a2=A[g][tg+4] a3=A[g+8][tg+4]
//   B: b0=B[pair tg][col g] b1=B[pair tg+4][col g]
//   C: c0=(g,2tg) c1=(g,2tg+1) c2=(g+8,2tg) c3=(g+8,2tg+1)
// ---------------------------------------------------------------------------
__device__ __forceinline__ uint2 split2(float e0, float e1) {
    // pack: low half = e0, high half = e1
    uint2 r;
    asm("cvt.rn.bf16x2.f32 %0, %1, %2;" : "=r"(r.x) : "f"(e1), "f"(e0));
    float h0 = __uint_as_float(r.x << 16);
    float h1 = __uint_as_float(r.x & 0xffff0000u);
    asm("cvt.rn.bf16x2.f32 %0, %1, %2;" : "=r"(r.y) : "f"(e1 - h1), "f"(e0 - h0));
    return r;
}
__device__ __forceinline__ void mmabf(float* c, unsigned a0, unsigned a1, unsigned a2,
                                      unsigned a3, unsigned b0, unsigned b1) {
    asm volatile("mma.sync.aligned.m16n8k16.row.col.f32.bf16.bf16.f32 "
                 "{%0,%1,%2,%3}, {%4,%5,%6,%7}, {%8,%9}, {%0,%1,%2,%3};"
                 : "+f"(c[0]), "+f"(c[1]), "+f"(c[2]), "+f"(c[3])
                 : "r"(a0), "r"(a1), "r"(a2), "r"(a3), "r"(b0), "r"(b1));
}
__device__ __forceinline__ void mma_x3b(float* c, const uint2 a[4], uint2 b0, uint2 b1) {
    mmabf(c, a[0].x, a[1].x, a[2].x, a[3].x, b0.x, b1.x);   // hi*hi
    mmabf(c, a[0].x, a[1].x, a[2].x, a[3].x, b0.y, b1.y);   // hi*lo
    mmabf(c, a[0].y, a[1].y, a[2].y, a[3].y, b0.x, b1.x);   // lo*hi
}

// ---------------------------------------------------------------------------
// Projection GEMM (bf16x3): C = A @ W^T + bias
// BM=128, BN=64, BK=32 (16 pairs), 256 threads = 8 warps (4m x 2n), warp 32x32.
// smem: As uint2[128][20], Ws uint2[64][20] = 30 KB. Row stride 20 pairs
// (40 words): fragment banks = 8g+2tg per phase -> conflict-free.
// mode 0: scatter into g_Q / g_K; mode 1: A = g_attn, plain write to Cout.
// ---------------------------------------------------------------------------
#define PROJ_SMEM ((128 * 20 + 64 * 20) * 8)

__global__ void __launch_bounds__(256)
proj_k(const float* __restrict__ A, const float* __restrict__ Wt,
       const float* __restrict__ bias, float* __restrict__ Cout, int mode)
{
    extern __shared__ uint2 psm[];
    uint2* As = psm;              // [128][20] pairs over k
    uint2* Ws = psm + 128 * 20;   // [64][20]

    const float* __restrict__ Ain = (mode == 1) ? g_attn : A;

    const int tid  = threadIdx.x;
    const int lane = tid & 31, warp = tid >> 5;
    const int g = lane >> 2, tg = lane & 3;
    const int wm = (warp >> 1) * 32;   // 0,32,64,96
    const int wn = (warp & 1) * 32;    // 0,32
    const int rowBase = blockIdx.y * 128;
    const int colBase = blockIdx.x * 64;

    float acc[2][4][4];
#pragma unroll
    for (int mt = 0; mt < 2; mt++)
#pragma unroll
        for (int nt = 0; nt < 4; nt++)
#pragma unroll
            for (int j = 0; j < 4; j++) acc[mt][nt][j] = 0.f;

    for (int kt = 0; kt < Dd; kt += 32) {
        __syncthreads();
        // A tile: 128x32 floats -> packed pairs
#pragma unroll
        for (int t = 0; t < 4; t++) {
            int idx = tid + t * 256;
            int r = idx >> 3, f4 = idx & 7;          // f4 -> floats 4f4..4f4+3
            float4 v = *(const float4*)(Ain + (size_t)(rowBase + r) * Dd + kt + f4 * 4);
            As[r * 20 + 2 * f4]     = split2(v.x, v.y);
            As[r * 20 + 2 * f4 + 1] = split2(v.z, v.w);
        }
        // W tile: 64x32 floats
#pragma unroll
        for (int t = 0; t < 2; t++) {
            int idx = tid + t * 256;
            int r = idx >> 3, f4 = idx & 7;
            float4 v = *(const float4*)(Wt + (size_t)(colBase + r) * Dd + kt + f4 * 4);
            Ws[r * 20 + 2 * f4]     = split2(v.x, v.y);
            Ws[r * 20 + 2 * f4 + 1] = split2(v.z, v.w);
        }
        __syncthreads();

#pragma unroll
        for (int kc = 0; kc < 2; kc++) {     // 2 x k16
            const int k0 = kc * 8;           // pair units
            uint2 af[2][4];
#pragma unroll
            for (int mt = 0; mt < 2; mt++) {
                int r0 = wm + mt * 16 + g;
                af[mt][0] = As[r0 * 20 + k0 + tg];
                af[mt][1] = As[(r0 + 8) * 20 + k0 + tg];
                af[mt][2] = As[r0 * 20 + k0 + tg + 4];
                af[mt][3] = As[(r0 + 8) * 20 + k0 + tg + 4];
            }
#pragma unroll
            for (int nt = 0; nt < 4; nt++) {
                int c0 = wn + nt * 8 + g;
                uint2 b0 = Ws[c0 * 20 + k0 + tg];
                uint2 b1 = Ws[c0 * 20 + k0 + tg + 4];
                mma_x3b(acc[0][nt], af[0], b0, b1);
                mma_x3b(acc[1][nt], af[1], b0, b1);
            }
        }
    }

    // Epilogue: bias + scatter
#pragma unroll
    for (int mt = 0; mt < 2; mt++)
#pragma unroll
    for (int nt = 0; nt < 4; nt++)
#pragma unroll
    for (int hf = 0; hf < 2; hf++) {
        int r = rowBase + wm + mt * 16 + g + hf * 8;
        int c = colBase + wn + nt * 8 + 2 * tg;
        float2 bv = *(const float2*)(bias + c);
        float2 v = make_float2(acc[mt][nt][hf * 2] + bv.x,
                               acc[mt][nt][hf * 2 + 1] + bv.y);
        int bb = r >> 11, s = r & 2047;
        if (mode == 0) {
            if (c < Dd) {
                int h = c >> 6, d0 = c & 63;
                *(float2*)&g_Q[(((size_t)(bb * Hh + h)) * Ss + s) * HDc + d0] = v;
            } else {
                int c2 = c - Dd; int h = c2 >> 6, d0 = c2 & 63;
                *(float2*)&g_K[(((size_t)(bb * Hh + h)) * Ss + s) * HDc + d0] = v;
            }
        } else {
            *(float2*)(Cout + (size_t)r * Dd + c) = v;
        }
    }
}

// ---------------------------------------------------------------------------
// bf16x3 flash attention, masked L1 renorm.
// CTA = (b,h, 128-query tile), 256 threads = 8 warps; warp w owns rows
// [16w,16w+16). P passes GEMM1->GEMM2 entirely in registers (C frag layout
// == A frag layout for m16n8k16). smem = Qs[128][36] + Ks[64][36] (pairs
// over d) + Vs[64][36] (pairs over KEYS, [d-col][keypair]) = 72 KB.
// ---------------------------------------------------------------------------
#define ATTN_SMEM ((128 * 36 + 64 * 36 + 64 * 36) * 8)

__global__ void __launch_bounds__(256, 2)
attn_k(const float* __restrict__ Vg, const float* __restrict__ Mg)
{
    extern __shared__ uint2 asm_[];
    uint2* Qs = asm_;               // [128][36] pairs over d
    uint2* Ks = Qs + 128 * 36;      // [64][36]  pairs over d, [key][dp]
    uint2* Vs = Ks + 64 * 36;       // [64][36]  pairs over keys, [d][kp]

    const int tid  = threadIdx.x;
    const int lane = tid & 31, w = tid >> 5;
    const int g = lane >> 2, tg = lane & 3;
    const int bh = blockIdx.y, bb = bh >> 4, h = bh & 15;
    const int q0 = blockIdx.x * 128;
    const int r0 = w * 16 + g;      // this thread's base row (and r0+8)

    // Q tile once: 128x64 floats -> packed pairs
    const float* __restrict__ gQ = g_Q + ((size_t)bh * Ss + q0) * HDc;
#pragma unroll
    for (int t = 0; t < 8; t++) {
        int idx = tid + t * 256;
        int r = idx >> 4, f4 = idx & 15;
        float4 v = *(const float4*)(gQ + (size_t)r * HDc + f4 * 4);
        Qs[r * 36 + 2 * f4]     = split2(v.x, v.y);
        Qs[r * 36 + 2 * f4 + 1] = split2(v.z, v.w);
    }

    float m_cur[2] = {-1e30f, -1e30f}, Zacc[2] = {0.f, 0.f}, Wacc[2] = {0.f, 0.f};
    float oacc[8][4];
#pragma unroll
    for (int nt = 0; nt < 8; nt++)
#pragma unroll
        for (int j = 0; j < 4; j++) oacc[nt][j] = 0.f;

    const float* __restrict__ mrow0 = Mg + ((size_t)(bb * Ss + q0 + r0)) * Ss;
    const float* __restrict__ mrow1 = mrow0 + (size_t)8 * Ss;

    for (int kt = 0; kt < Ss; kt += 64) {
        __syncthreads();   // prev iter's GEMMs done with Ks/Vs (+ Q visible)

        // K tile [key][d]: 64x64 floats -> pairs over d
        const float* __restrict__ gK = g_K + ((size_t)bh * Ss + kt) * HDc;
#pragma unroll
        for (int t = 0; t < 4; t++) {
            int idx = tid + t * 256;
            int r = idx >> 4, f4 = idx & 15;
            float4 v = *(const float4*)(gK + (size_t)r * HDc + f4 * 4);
            Ks[r * 36 + 2 * f4]     = split2(v.x, v.y);
            Ks[r * 36 + 2 * f4 + 1] = split2(v.z, v.w);
        }
        // V tile -> TRANSPOSED pairs over keys: Vs[d][kp] = {V[2kp][d], V[2kp+1][d]}
        const float* __restrict__ gV =
            Vg + (((size_t)(bb * Ss + kt)) * Hh + h) * HDc;
#pragma unroll
        for (int t = 0; t < 2; t++) {
            int idx = tid + t * 256;
            int kp = idx & 31;               // key pair
            int n4 = (idx >> 5) << 2;        // d column group
            float4 v0 = *(const float4*)(gV + (size_t)(2 * kp) * (Hh * HDc) + n4);
            float4 v1 = *(const float4*)(gV + (size_t)(2 * kp + 1) * (Hh * HDc) + n4);
            Vs[(n4 + 0) * 36 + kp] = split2(v0.x, v1.x);
            Vs[(n4 + 1) * 36 + kp] = split2(v0.y, v1.y);
            Vs[(n4 + 2) * 36 + kp] = split2(v0.z, v1.z);
            Vs[(n4 + 3) * 36 + kp] = split2(v0.w, v1.w);
        }
        // Prefetch mask fragments (hidden under GEMM1)
        float2 mk0[8], mk1[8];
#pragma unroll
        for (int nt = 0; nt < 8; nt++) {
            mk0[nt] = *(const float2*)(mrow0 + kt + nt * 8 + 2 * tg);
            mk1[nt] = *(const float2*)(mrow1 + kt + nt * 8 + 2 * tg);
        }
        __syncthreads();

        // GEMM1: S = Q K^T   (k = d, 4 x k16)
        float sfr[8][4];
#pragma unroll
        for (int nt = 0; nt < 8; nt++)
#pragma unroll
            for (int j = 0; j < 4; j++) sfr[nt][j] = 0.f;
#pragma unroll
        for (int kc = 0; kc < 4; kc++) {
            const int k0 = kc * 8;
            uint2 qf[4];
            qf[0] = Qs[r0 * 36 + k0 + tg];
            qf[1] = Qs[(r0 + 8) * 36 + k0 + tg];
            qf[2] = Qs[r0 * 36 + k0 + tg + 4];
            qf[3] = Qs[(r0 + 8) * 36 + k0 + tg + 4];
#pragma unroll
            for (int nt = 0; nt < 8; nt++) {
                int c = nt * 8 + g;
                uint2 b0 = Ks[c * 36 + k0 + tg];
                uint2 b1 = Ks[c * 36 + k0 + tg + 4];
                mma_x3b(sfr[nt], qf, b0, b1);
            }
        }

        // Softmax stats; overwrite sfr with P = exp(s - m_new) * mask
        float rmax0 = -1e30f, rmax1 = -1e30f;
#pragma unroll
        for (int nt = 0; nt < 8; nt++) {
            sfr[nt][0] *= SCALE; sfr[nt][1] *= SCALE;
            sfr[nt][2] *= SCALE; sfr[nt][3] *= SCALE;
            rmax0 = fmaxf(rmax0, fmaxf(sfr[nt][0], sfr[nt][1]));
            rmax1 = fmaxf(rmax1, fmaxf(sfr[nt][2], sfr[nt][3]));
        }
        rmax0 = fmaxf(rmax0, __shfl_xor_sync(0xffffffffu, rmax0, 1));
        rmax0 = fmaxf(rmax0, __shfl_xor_sync(0xffffffffu, rmax0, 2));
        rmax1 = fmaxf(rmax1, __shfl_xor_sync(0xffffffffu, rmax1, 1));
        rmax1 = fmaxf(rmax1, __shfl_xor_sync(0xffffffffu, rmax1, 2));
        float mn0 = fmaxf(m_cur[0], rmax0), mn1 = fmaxf(m_cur[1], rmax1);
        float al0 = __expf(m_cur[0] - mn0), al1 = __expf(m_cur[1] - mn1);

        float zp0 = 0.f, zp1 = 0.f, wp0 = 0.f, wp1 = 0.f;
#pragma unroll
        for (int nt = 0; nt < 8; nt++) {
            float p00 = __expf(sfr[nt][0] - mn0), p01 = __expf(sfr[nt][1] - mn0);
            float p10 = __expf(sfr[nt][2] - mn1), p11 = __expf(sfr[nt][3] - mn1);
            zp0 += p00 + p01; zp1 += p10 + p11;
            sfr[nt][0] = p00 * mk0[nt].x; sfr[nt][1] = p01 * mk0[nt].y;
            sfr[nt][2] = p10 * mk1[nt].x; sfr[nt][3] = p11 * mk1[nt].y;
            wp0 += sfr[nt][0] + sfr[nt][1];
            wp1 += sfr[nt][2] + sfr[nt][3];
        }
        zp0 += __shfl_xor_sync(0xffffffffu, zp0, 1); zp0 += __shfl_xor_sync(0xffffffffu, zp0, 2);
        zp1 += __shfl_xor_sync(0xffffffffu, zp1, 1); zp1 += __shfl_xor_sync(0xffffffffu, zp1, 2);
        wp0 += __shfl_xor_sync(0xffffffffu, wp0, 1); wp0 += __shfl_xor_sync(0xffffffffu, wp0, 2);
        wp1 += __shfl_xor_sync(0xffffffffu, wp1, 1); wp1 += __shfl_xor_sync(0xffffffffu, wp1, 2);
        Zacc[0] = Zacc[0] * al0 + zp0; Zacc[1] = Zacc[1] * al1 + zp1;
        Wacc[0] = Wacc[0] * al0 + wp0; Wacc[1] = Wacc[1] * al1 + wp1;
        m_cur[0] = mn0; m_cur[1] = mn1;

        // GEMM2: O = O*alpha + P V   (k = keys; P straight from registers:
        // GEMM1 C-frag (g,2tg) == A-frag pair tg for m16n8k16)
#pragma unroll
        for (int nt = 0; nt < 8; nt++) {
            oacc[nt][0] *= al0; oacc[nt][1] *= al0;
            oacc[nt][2] *= al1; oacc[nt][3] *= al1;
        }
#pragma unroll
        for (int kc = 0; kc < 4; kc++) {      // key chunks of 16
            uint2 pa[4];
            pa[0] = split2(sfr[2 * kc][0],     sfr[2 * kc][1]);     // row g,   pair tg
            pa[1] = split2(sfr[2 * kc][2],     sfr[2 * kc][3]);     // row g+8, pair tg
            pa[2] = split2(sfr[2 * kc + 1][0], sfr[2 * kc + 1][1]); // row g,   pair tg+4
            pa[3] = split2(sfr[2 * kc + 1][2], sfr[2 * kc + 1][3]); // row g+8, pair tg+4
            const int k0 = kc * 8;
#pragma unroll
            for (int nt = 0; nt < 8; nt++) {
                int c = nt * 8 + g;
                uint2 b0 = Vs[c * 36 + k0 + tg];
                uint2 b1 = Vs[c * 36 + k0 + tg + 4];
                mma_x3b(oacc[nt], pa, b0, b1);
            }
        }
    }

    // Epilogue: divide and write [B,S,D]
    float inv0 = 1.f / (Wacc[0] + 1e-8f * Zacc[0]);
    float inv1 = 1.f / (Wacc[1] + 1e-8f * Zacc[1]);
    int s0 = q0 + r0;
#pragma unroll
    for (int nt = 0; nt < 8; nt++) {
        int c = h * HDc + nt * 8 + 2 * tg;
        *(float2*)&g_attn[((size_t)(bb * Ss + s0)) * Dd + c] =
            make_float2(oacc[nt][0] * inv0, oacc[nt][1] * inv0);
        *(float2*)&g_attn[((size_t)(bb * Ss + s0 + 8)) * Dd + c] =
            make_float2(oacc[nt][2] * inv1, oacc[nt][3] * inv1);
    }
}

// ---------------------------------------------------------------------------
extern "C" void kernel_launch(void* const* d_in, const int* in_sizes, int n_in,
                              void* d_out, int out_size)
{
    const float* x     = (const float*)d_in[0];
    const float* V     = (const float*)d_in[1];
    const float* M     = (const float*)d_in[2];
    const float* in_w  = (const float*)d_in[3];
    const float* in_b  = (const float*)d_in[4];
    const float* out_w = (const float*)d_in[5];
    const float* out_b = (const float*)d_in[6];
    float* out = (float*)d_out;

    cudaFuncSetAttribute((const void*)proj_k,
                         cudaFuncAttributeMaxDynamicSharedMemorySize, PROJ_SMEM);
    cudaFuncSetAttribute((const void*)attn_k,
                         cudaFuncAttributeMaxDynamicSharedMemorySize, ATTN_SMEM);

    // 1) QK projection: [4096,1024] x [2048,1024]^T -> scatter to g_Q/g_K
    proj_k<<<dim3(32, 32), 256, PROJ_SMEM>>>(x, in_w, in_b, nullptr, 0);
    // 2) masked-renorm flash attention (bf16x3 tensor cores) -> g_attn
    attn_k<<<dim3(16, 32), 256, ATTN_SMEM>>>(V, M);
    // 3) out projection: g_attn x out_w^T + out_b -> d_out
    proj_k<<<dim3(16, 32), 256, PROJ_SMEM>>>(nullptr, out_w, out_b, out, 1);
}